// round 12
// baseline (speedup 1.0000x reference)
#include <cuda_runtime.h>
#include <cuda_bf16.h>
#include <cstdint>

#define DINL __device__ __forceinline__

// pre-rounded tf32 weights: [pass 2][tap 9][n=co 64][128B]
// 128B row = 32 tf32 (k=ci of pass); 8 x 16B granules, granule g stored at (g ^ (n&7))
__device__ __align__(16) unsigned char g_wsw[2 * 9 * 64 * 128];

constexpr uint32_t AROWSZ = 130 * 128;           // 16640 B per staged input row
constexpr uint32_t SA    = 0;                    // A ping-pong: 2 x 16640 = 33280
constexpr uint32_t SBUF  = 33280;                // B stages: 4 x 8192 = 32768
constexpr uint32_t SBAR  = 33280 + 32768;        // 66048
constexpr uint32_t SMEMSZ = SBAR + 64;           // 8 B-mbarriers

// ---------------- ptx helpers ----------------
DINL uint32_t s2u(const void* p){uint32_t a;asm("{.reg .u64 t; cvta.to.shared.u64 t,%1; cvt.u32.u64 %0,t;}":"=r"(a):"l"(p));return a;}
DINL void bar_init(uint32_t a,uint32_t c){asm volatile("mbarrier.init.shared.b64 [%0],%1;"::"r"(a),"r"(c):"memory");}
DINL void bar_arrive(uint32_t a){asm volatile("mbarrier.arrive.shared.b64 _,[%0];"::"r"(a):"memory");}
DINL void bar_expect_tx(uint32_t a,uint32_t b){asm volatile("mbarrier.arrive.expect_tx.shared.b64 _,[%0],%1;"::"r"(a),"r"(b):"memory");}
DINL void bar_wait(uint32_t a,uint32_t ph){
  uint32_t done;
  asm volatile("{\n\t"
               ".reg .pred p;\n\t"
               "mbarrier.try_wait.parity.acquire.cta.shared::cta.b64 p,[%1],%2;\n\t"
               "selp.b32 %0,1,0,p;\n\t"
               "}"
               :"=r"(done):"r"(a),"r"(ph):"memory");
  if(!done){
    asm volatile("{\n\t"
                 ".reg .pred P1;\n\t"
                 "WAIT_LOOP_%=:\n\t"
                 "mbarrier.try_wait.parity.acquire.cta.shared::cta.b64 P1,[%0],%1,0x989680;\n\t"
                 "@P1 bra.uni WAIT_DONE_%=;\n\t"
                 "bra.uni WAIT_LOOP_%=;\n\t"
                 "WAIT_DONE_%=:\n\t"
                 "}"
                 ::"r"(a),"r"(ph):"memory");
  }
}
DINL void bulk_cp(uint32_t dst,const void* src,uint32_t bytes,uint32_t mbar){
  asm volatile("cp.async.bulk.shared::cluster.global.mbarrier::complete_tx::bytes [%0],[%1],%2,[%3];"
               ::"r"(dst),"l"(src),"r"(bytes),"r"(mbar):"memory");
}
DINL void ldsm4(uint32_t* r, uint32_t a){
  asm volatile("ldmatrix.sync.aligned.m8n8.x4.shared.b16 {%0,%1,%2,%3},[%4];"
               :"=r"(r[0]),"=r"(r[1]),"=r"(r[2]),"=r"(r[3]):"r"(a));
}
DINL void mma(float* c, const uint32_t* a, uint32_t b0, uint32_t b1){
  asm volatile("mma.sync.aligned.m16n8k8.row.col.f32.tf32.tf32.f32 "
               "{%0,%1,%2,%3},{%4,%5,%6,%7},{%8,%9},{%0,%1,%2,%3};"
               :"+f"(c[0]),"+f"(c[1]),"+f"(c[2]),"+f"(c[3])
               :"r"(a[0]),"r"(a[1]),"r"(a[2]),"r"(a[3]),"r"(b0),"r"(b1));
}
DINL uint32_t f2tf(float f){uint32_t u;asm("cvt.rna.tf32.f32 %0,%1;":"=r"(u):"f"(f));return u;}

// ---------------- weight prep: tf32 round + swizzle ----------------
__global__ void prep_w(const float* __restrict__ wgt){
  int tap = blockIdx.x, co = threadIdx.x;   // <<<9, 64>>>
  uint32_t sw = (uint32_t)co & 7u;
  for (int p = 0; p < 2; p++){
    unsigned char* base = g_wsw + ((size_t)(p*9 + tap)*64 + co)*128;
    for (int k = 0; k < 32; k++){
      float v = wgt[co*576 + (p*32 + k)*9 + tap];
      uint32_t g = (uint32_t)(k >> 2), pos = ((uint32_t)k & 3u)*4u;
      *(uint32_t*)(base + ((g ^ sw) << 4) + pos) = f2tf(v);
    }
  }
}

// ---------------- staging helper: one slot (32 tf32, swizzled) ----------------
DINL void store_unit(unsigned char* smem, uint32_t addr, uint32_t swz, const float* v){
  #pragma unroll
  for (int g = 0; g < 8; g++){
    uint4 q;
    q.x = f2tf(v[g*4 + 0]);
    q.y = f2tf(v[g*4 + 1]);
    q.z = f2tf(v[g*4 + 2]);
    q.w = f2tf(v[g*4 + 3]);
    *(uint4*)(smem + addr + ((((uint32_t)g) ^ swz) << 4)) = q;
  }
}

// ---------------- main kernel ----------------
__global__ __launch_bounds__(256, 2)
void conv_mma(const float* __restrict__ x,
              const float* __restrict__ bias,
              float* __restrict__ out)
{
  extern __shared__ __align__(128) unsigned char smem[];
  const uint32_t sb = s2u(smem);
  const int tid = threadIdx.x, wid = tid >> 5, lane = tid & 31;
  const int half = blockIdx.x, h = blockIdx.y, b = blockIdx.z;

  // B barriers only: BFULL[0..3]@+0, BEMPTY[0..3]@+32
  const uint32_t BARB = sb + SBAR;

  if (tid == 0){
    #pragma unroll
    for (int s = 0; s < 4; s++){
      bar_init(BARB + s*8, 1);            // B full: tx-based
      bar_init(BARB + 32 + s*8, 4);       // B empty: 4 compute warps (lane 0)
    }
  }
  __syncthreads();
  if (tid == 0){
    #pragma unroll
    for (int s = 0; s < 4; s++){
      bar_expect_tx(BARB + s*8, 8192u);
      bulk_cp(sb + SBUF + (uint32_t)s*8192u, g_wsw + (size_t)s*8192, 8192u, BARB + s*8);
    }
  }

  float acc[2][8][4];
  #pragma unroll
  for (int i = 0; i < 2; i++)
    #pragma unroll
    for (int j = 0; j < 8; j++)
      #pragma unroll
      for (int k = 0; k < 4; k++) acc[i][j][k] = 0.f;

  // lane-dependent compute constants
  const uint32_t s0     = (uint32_t)(wid*32) + (uint32_t)(lane & 15);  // A slot base
  const uint32_t gha    = (uint32_t)(lane >> 4);                        // A granule select
  const uint32_t co_off = (uint32_t)((lane & 7) + (((lane >> 4) & 1) << 3));
  const uint32_t eb     = (uint32_t)(((lane >> 3) & 1) ^ (lane & 7));   // B granule xor key

  // 7 steps: at step s, staging warps fill row s into buf[s&1],
  //          compute warps consume row s-1 from buf[(s-1)&1].
  #pragma unroll 1
  for (int step = 0; step < 7; step++){
    if (wid >= 4 && step < 6){
      // ---------------- staging warps (4-7): fill row 'step' ----------------
      const int r = step;                       // r = p*3 + khr
      const int p = (r >= 3) ? 1 : 0;
      const int khr = r - 3*p;
      const uint32_t Abase = SA + (uint32_t)(r & 1)*AROWSZ;
      const int wt = tid - 128;                 // 0..127
      const int y = h + khr - 1;
      const bool vy = (unsigned)y < 256u;
      {
        int s = wt + 1;                         // slots 1..128: w always in-range
        int w = half*128 + s - 1;
        const float* xp = x + ((((size_t)b*64 + p*32)*256 + (size_t)(vy ? y : 0))*256) + w;
        float v[32];
        #pragma unroll
        for (int ci = 0; ci < 32; ci++)
          v[ci] = vy ? xp[(size_t)ci * 65536] : 0.f;
        store_unit(smem, Abase + (uint32_t)s*128u, (uint32_t)s & 7u, v);
      }
      if (wt == 0 || wt == 127){                // edge slots 0 and 129
        int s = (wt == 0) ? 0 : 129;
        int w = half*128 + s - 1;
        bool ok = vy && ((unsigned)w < 256u);
        const float* xp = x + ((((size_t)b*64 + p*32)*256 + (size_t)(ok ? y : 0))*256) + (ok ? w : 0);
        float v[32];
        #pragma unroll
        for (int ci = 0; ci < 32; ci++)
          v[ci] = ok ? xp[(size_t)ci * 65536] : 0.f;
        store_unit(smem, Abase + (uint32_t)s*128u, (uint32_t)s & 7u, v);
      }
    }

    if (wid < 4 && step >= 1){
      // ---------------- compute warps (0-3): consume row 'step-1' ----------------
      const int r = step - 1;
      const uint32_t Aslot = sb + SA + (uint32_t)(r & 1)*AROWSZ;

      #pragma unroll 1
      for (int kw = 0; kw < 3; kw++){
        const int it = r*3 + kw;               // linear tap-pass index 0..17
        const int st = it & 3;
        const uint32_t fullb  = BARB + (uint32_t)st*8u;
        const uint32_t emptyb = BARB + 32u + (uint32_t)st*8u;
        bar_wait(fullb, (uint32_t)((it >> 2) & 1));

        const uint32_t arow = s0 + (uint32_t)kw;
        const uint32_t Aa0  = Aslot + arow*128u;
        const uint32_t ea   = gha ^ (arow & 7u);
        const uint32_t Bt   = sb + SBUF + (uint32_t)st*8192u + co_off*128u;
        #pragma unroll
        for (int ks = 0; ks < 4; ks++){
          const uint32_t bofs = (uint32_t)(((2*ks) ^ (int)eb) << 4);
          uint32_t br[16];
          ldsm4(br + 0,  Bt + bofs);
          ldsm4(br + 4,  Bt + 2048u + bofs);
          ldsm4(br + 8,  Bt + 4096u + bofs);
          ldsm4(br + 12, Bt + 6144u + bofs);
          const uint32_t aofs = (uint32_t)(((2*ks) ^ (int)ea) << 4);
          #pragma unroll
          for (int mf = 0; mf < 2; mf++){
            uint32_t ar[4];
            ldsm4(ar, Aa0 + (uint32_t)mf*2048u + aofs);
            #pragma unroll
            for (int nf = 0; nf < 8; nf++)
              mma(acc[mf][nf], ar, br[nf*2], br[nf*2 + 1]);
          }
        }

        if (lane == 0) bar_arrive(emptyb);
        if (wid == 0 && lane == 0 && it < 14){
          bar_wait(emptyb, (uint32_t)((it >> 2) & 1));
          bar_expect_tx(fullb, 8192u);
          bulk_cp(sb + SBUF + (uint32_t)st*8192u,
                  g_wsw + (size_t)(it + 4)*8192, 8192u, fullb);
        }
      }
    }

    __syncthreads();   // row handoff: producer/consumer fence + buffer swap
  }

  // ---- epilogue ----
  if (wid < 4){
    #pragma unroll
    for (int mf = 0; mf < 2; mf++){
      #pragma unroll
      for (int nf = 0; nf < 8; nf++){
        int co = nf*8 + 2*(lane & 3);
        int wo = half*128 + wid*32 + mf*16 + (lane >> 2);
        float b0 = bias[co], b1 = bias[co + 1];
        size_t o0 = (((size_t)b*64 + co)*256 + h)*256 + wo;
        out[o0]             = acc[mf][nf][0] + b0;
        out[o0 + 65536]     = acc[mf][nf][1] + b1;
        out[o0 + 8]         = acc[mf][nf][2] + b0;
        out[o0 + 65536 + 8] = acc[mf][nf][3] + b1;
      }
    }
  }
}

// ---------------- launch ----------------
extern "C" void kernel_launch(void* const* d_in, const int* in_sizes, int n_in,
                              void* d_out, int out_size)
{
  (void)in_sizes; (void)n_in; (void)out_size;
  const float* x    = (const float*)d_in[0];
  const float* wgt  = (const float*)d_in[1];
  const float* bias = (const float*)d_in[2];
  float* out        = (float*)d_out;

  cudaFuncSetAttribute(conv_mma, cudaFuncAttributeMaxDynamicSharedMemorySize, SMEMSZ);

  prep_w<<<9, 64>>>(wgt);
  dim3 grid(2, 256, 16);   // (w-half, h, b) = 8192 CTAs
  conv_mma<<<grid, 256, SMEMSZ>>>(x, bias, out);
}